// round 6
// baseline (speedup 1.0000x reference)
#include <cuda_runtime.h>
#include <cuda_bf16.h>
#include <math.h>
#include <stdint.h>

#define BSZ 256
#define D   512
#define KC  64
#define NKC 8
#define HALF 128
#define GROW 257
#define NEG (-1.0e30f)

// ---- smem layout (bytes) ----
#define A0_OFF 0
#define B0_OFF 16384
#define A1_OFF 49152
#define B1_OFF 65536           /* buffers end at 98304 */
#define G_OFF  0               /* G [128][257] f32 = 131584, union with buffers */
#define COLM_OFF 131584
#define COLS_OFF 132608
#define ROWM_OFF 133632
#define ROWS_OFF 134144
#define PLANE_OFF 134656
#define SMEM_BYTES 134672

#define SW(o) ((o) ^ ((((unsigned)(o))>>3)&0x70u))

// ---- device scratch ----
__device__ __nv_bfloat16 g_Yb[BSZ*D];
__device__ float g_px_m[BSZ*BSZ];
__device__ float g_px_s[BSZ*BSZ];
__device__ float g_py_m[BSZ*BSZ];
__device__ float g_py_s[BSZ*BSZ];
__device__ float g_lse_z[BSZ];

static __device__ __forceinline__ uint32_t smem_u32(const void* p){
    uint32_t a;
    asm("{ .reg .u64 t; cvta.to.shared.u64 t, %1; cvt.u32.u64 %0, t; }" : "=r"(a) : "l"(p));
    return a;
}

#define LDSM_X4(r0,r1,r2,r3, addr) \
    asm volatile("ldmatrix.sync.aligned.m8n8.x4.shared.b16 {%0,%1,%2,%3}, [%4];" \
        : "=r"(r0),"=r"(r1),"=r"(r2),"=r"(r3) : "r"(addr))

__device__ __forceinline__ void lse_merge(float& M, float& S, float m2, float s2){
    if (m2 > M){ S = S * __expf(M - m2) + s2; M = m2; }
    else       { S = S + s2 * __expf(m2 - M); }
}

__global__ void conv_y_kernel(const float* __restrict__ Y){
    int i = blockIdx.x * blockDim.x + threadIdx.x;
    g_Yb[i] = __float2bfloat16(Y[i]);
}

// ---- pipeline stage helpers ----
static __device__ __forceinline__ void ldg_x(const float* __restrict__ X,
                                             int aBase, int k0, int tid, float4 xr[4]){
    int row = tid >> 2, seg = tid & 3;
    const float4* Xp = (const float4*)(X + (size_t)(aBase + row)*D + k0 + seg*16);
    #pragma unroll
    for (int i = 0; i < 4; ++i) xr[i] = Xp[i];
}
static __device__ __forceinline__ void cpasync_y(uint32_t sb, int k0, int bufB, int tid){
    #pragma unroll
    for (int i = 0; i < 4; ++i){
        int gi = tid + 512*i;
        int row = gi >> 3, u = gi & 7;
        const void* src = (const void*)(g_Yb + (size_t)row*D + k0 + u*8);
        uint32_t dst = sb + bufB + SW((uint32_t)(row*128 + u*16));
        asm volatile("cp.async.cg.shared.global [%0], [%1], 16;"
            :: "r"(dst), "l"(__cvta_generic_to_global(src)) : "memory");
    }
    asm volatile("cp.async.commit_group;" ::: "memory");
}
static __device__ __forceinline__ void sts_w(const float* __restrict__ Z, char* smem,
                                             int s, int k0, int bufA, int tid,
                                             const float4 xr[4]){
    int row = tid >> 2, seg = tid & 3;
    const float4* Zp = (const float4*)(Z + (size_t)s*D + k0 + seg*16);
    uint32_t v[8];
    #pragma unroll
    for (int i = 0; i < 4; ++i){
        float4 xv = xr[i], zv = Zp[i];
        __nv_bfloat162 p0 = __floats2bfloat162_rn(xv.x*zv.x, xv.y*zv.y);
        __nv_bfloat162 p1 = __floats2bfloat162_rn(xv.z*zv.z, xv.w*zv.w);
        v[2*i]   = *(uint32_t*)&p0;
        v[2*i+1] = *(uint32_t*)&p1;
    }
    uint32_t off = (uint32_t)(row*128 + seg*32);
    *(uint4*)(smem + bufA + SW(off))      = make_uint4(v[0], v[1], v[2], v[3]);
    *(uint4*)(smem + bufA + SW(off + 16)) = make_uint4(v[4], v[5], v[6], v[7]);
}

__global__ void __launch_bounds__(512, 1)
symile_main(const float* __restrict__ X, const float* __restrict__ Z){
    extern __shared__ char smem[];
    const uint32_t sb = smem_u32(smem);
    const int tid = threadIdx.x, warp = tid >> 5, lane = tid & 31;
    const int s = blockIdx.x;
    const int wm = warp & 3, wn = warp >> 2;       // 4x4 warp grid: 32-row x 64-col
    const int lrow = lane & 7, lsel = lane >> 3;   // ldmatrix addressing
    const int g = lane >> 2, tg = lane & 3;        // mma accumulator layout

    float* G    = (float*)(smem + G_OFF);
    float* colM = (float*)(smem + COLM_OFF);
    float* colS = (float*)(smem + COLS_OFF);
    float* rowM = (float*)(smem + ROWM_OFF);
    float* rowS = (float*)(smem + ROWS_OFF);
    float* plane= (float*)(smem + PLANE_OFF);

    if (tid < BSZ){ colM[tid] = NEG; colS[tid] = 0.f; }
    if (tid == 0){ plane[0] = NEG; plane[1] = 0.f; }

    for (int half = 0; half < 2; ++half){
        const int aBase = half * HALF;
        float c[2][8][4];
        #pragma unroll
        for (int mt = 0; mt < 2; ++mt)
            #pragma unroll
            for (int nt = 0; nt < 8; ++nt)
                #pragma unroll
                for (int i = 0; i < 4; ++i) c[mt][nt][i] = 0.f;

        // ---- prologue: chunk 0 -> buf0 ----
        {
            float4 xr[4];
            ldg_x(X, aBase, 0, tid, xr);
            cpasync_y(sb, 0, B0_OFF, tid);
            sts_w(Z, smem, s, 0, A0_OFF, tid, xr);
            asm volatile("cp.async.wait_group 0;" ::: "memory");
            __syncthreads();
        }

        for (int kc = 0; kc < NKC; ++kc){
            const int b = kc & 1, nb = b ^ 1;
            float4 xr[4];
            if (kc < NKC-1){
                ldg_x(X, aBase, (kc+1)*KC, tid, xr);            // in-flight over mma
                cpasync_y(sb, (kc+1)*KC, nb ? B1_OFF : B0_OFF, tid);
            }
            const uint32_t sA = sb + (b ? A1_OFF : A0_OFF);
            const uint32_t sB = sb + (b ? B1_OFF : B0_OFF);
            #pragma unroll
            for (int ks = 0; ks < 4; ++ks){
                unsigned a[2][4], bb[8][2];
                // A: 2 tiles of 16x16, ldmatrix.x4 each
                {
                    uint32_t arow = (uint32_t)(wm*32 + (lsel & 1)*8 + lrow);
                    uint32_t acol = (uint32_t)(ks*32 + (lsel >> 1)*16);
                    #pragma unroll
                    for (int mt = 0; mt < 2; ++mt){
                        uint32_t o = (arow + mt*16)*128 + acol;
                        LDSM_X4(a[mt][0], a[mt][1], a[mt][2], a[mt][3], sA + SW(o));
                    }
                }
                // B: 4 pairs of n-tiles, ldmatrix.x4 each
                {
                    uint32_t brow = (uint32_t)(wn*64 + (lsel >> 1)*8 + lrow);
                    uint32_t bcol = (uint32_t)(ks*32 + (lsel & 1)*16);
                    #pragma unroll
                    for (int p = 0; p < 4; ++p){
                        uint32_t o = (brow + p*16)*128 + bcol;
                        LDSM_X4(bb[2*p][0], bb[2*p][1], bb[2*p+1][0], bb[2*p+1][1],
                                sB + SW(o));
                    }
                }
                #pragma unroll
                for (int mt = 0; mt < 2; ++mt)
                    #pragma unroll
                    for (int nt = 0; nt < 8; ++nt)
                        asm volatile(
                          "mma.sync.aligned.m16n8k16.row.col.f32.bf16.bf16.f32 "
                          "{%0,%1,%2,%3}, {%4,%5,%6,%7}, {%8,%9}, {%0,%1,%2,%3};\n"
                          : "+f"(c[mt][nt][0]), "+f"(c[mt][nt][1]),
                            "+f"(c[mt][nt][2]), "+f"(c[mt][nt][3])
                          : "r"(a[mt][0]), "r"(a[mt][1]), "r"(a[mt][2]), "r"(a[mt][3]),
                            "r"(bb[nt][0]), "r"(bb[nt][1]));
            }
            if (kc < NKC-1){
                sts_w(Z, smem, s, (kc+1)*KC, nb ? A1_OFF : A0_OFF, tid, xr);
                asm volatile("cp.async.wait_group 0;" ::: "memory");
            }
            __syncthreads();   // publish next buffer / retire reads of current
        }

        // ---- spill accumulators: G[128][256] for this half ----
        #pragma unroll
        for (int mt = 0; mt < 2; ++mt)
            #pragma unroll
            for (int nt = 0; nt < 8; ++nt){
                int row = wm*32 + mt*16 + g;
                int col = wn*64 + nt*8 + tg*2;
                G[row*GROW + col]         = c[mt][nt][0];
                G[row*GROW + col + 1]     = c[mt][nt][1];
                G[(row+8)*GROW + col]     = c[mt][nt][2];
                G[(row+8)*GROW + col + 1] = c[mt][nt][3];
            }
        __syncthreads();

        // ---- row reduce: per-a LSE partial over r (anchor-x) ----
        {
            int row = tid >> 2, part = tid & 3;
            const float* Gr = G + row*GROW + part*64;
            float m = NEG;
            #pragma unroll 8
            for (int cc = 0; cc < 64; ++cc) m = fmaxf(m, Gr[cc]);
            m = fmaxf(m, __shfl_xor_sync(0xffffffffu, m, 1));
            m = fmaxf(m, __shfl_xor_sync(0xffffffffu, m, 2));
            float sum = 0.f;
            #pragma unroll 8
            for (int cc = 0; cc < 64; ++cc) sum += __expf(Gr[cc] - m);
            sum += __shfl_xor_sync(0xffffffffu, sum, 1);
            sum += __shfl_xor_sync(0xffffffffu, sum, 2);
            if (part == 0){
                int a_glob = aBase + row;
                g_px_m[s*BSZ + a_glob] = m;
                g_px_s[s*BSZ + a_glob] = sum;
                rowM[row] = m; rowS[row] = sum;
            }
        }
        // ---- col reduce: per-r LSE partial over a (anchor-y) ----
        {
            int col = tid >> 1, part = tid & 1;
            const float* Gc = G + part*64*GROW + col;
            float m = NEG;
            #pragma unroll 8
            for (int rr = 0; rr < 64; ++rr) m = fmaxf(m, Gc[rr*GROW]);
            m = fmaxf(m, __shfl_xor_sync(0xffffffffu, m, 1));
            float sum = 0.f;
            #pragma unroll 8
            for (int rr = 0; rr < 64; ++rr) sum += __expf(Gc[rr*GROW] - m);
            sum += __shfl_xor_sync(0xffffffffu, sum, 1);
            if (part == 0) lse_merge(colM[col], colS[col], m, sum);
        }
        __syncthreads();
        // ---- plane reduce (anchor-z) ----
        if (warp == 0){
            float M = NEG, S = 0.f;
            #pragma unroll
            for (int j = 0; j < 4; ++j) lse_merge(M, S, rowM[lane + j*32], rowS[lane + j*32]);
            #pragma unroll
            for (int off = 16; off > 0; off >>= 1){
                float m2 = __shfl_xor_sync(0xffffffffu, M, off);
                float s2 = __shfl_xor_sync(0xffffffffu, S, off);
                lse_merge(M, S, m2, s2);
            }
            if (lane == 0) lse_merge(plane[0], plane[1], M, S);
        }
        __syncthreads();   // G/buffer region free for next half
    }

    if (tid < BSZ){
        g_py_m[s*BSZ + tid] = colM[tid];
        g_py_s[s*BSZ + tid] = colS[tid];
    }
    if (tid == 0) g_lse_z[s] = plane[0] + logf(plane[1]);
}

__global__ void symile_finalize(const float* __restrict__ X, const float* __restrict__ Y,
                                const float* __restrict__ Z, float* __restrict__ out){
    __shared__ float red[BSZ];
    const int t = threadIdx.x;
    float M = NEG, S = 0.f;
    for (int si = 0; si < BSZ; ++si)
        lse_merge(M, S, g_px_m[si*BSZ + t], g_px_s[si*BSZ + t]);
    const float lx = M + logf(S);
    M = NEG; S = 0.f;
    for (int si = 0; si < BSZ; ++si)
        lse_merge(M, S, g_py_m[si*BSZ + t], g_py_s[si*BSZ + t]);
    const float ly = M + logf(S);
    const float lz = g_lse_z[t];
    float diag = 0.f;
    for (int dd = 0; dd < D; dd += 4){
        float4 xv = *(const float4*)(X + t*D + dd);
        float4 yv = *(const float4*)(Y + t*D + dd);
        float4 zv = *(const float4*)(Z + t*D + dd);
        diag += xv.x*yv.x*zv.x + xv.y*yv.y*zv.y + xv.z*yv.z*zv.z + xv.w*yv.w*zv.w;
    }
    red[t] = lx + ly + lz - 3.f*diag;
    __syncthreads();
    for (int off = 128; off > 0; off >>= 1){
        if (t < off) red[t] += red[t + off];
        __syncthreads();
    }
    if (t == 0) out[0] = red[0] / 768.f;
}

extern "C" void kernel_launch(void* const* d_in, const int* in_sizes, int n_in,
                              void* d_out, int out_size){
    const float* X = (const float*)d_in[0];
    const float* Y = (const float*)d_in[1];
    const float* Z = (const float*)d_in[2];
    float* out = (float*)d_out;

    cudaFuncSetAttribute(symile_main, cudaFuncAttributeMaxDynamicSharedMemorySize, SMEM_BYTES);

    conv_y_kernel<<<(BSZ*D)/256, 256>>>(Y);
    symile_main<<<BSZ, 512, SMEM_BYTES>>>(X, Z);
    symile_finalize<<<1, BSZ>>>(X, Y, Z, out);
}

// round 7
// speedup vs baseline: 1.3595x; 1.3595x over previous
#include <cuda_runtime.h>
#include <cuda_bf16.h>
#include <math.h>
#include <stdint.h>

#define BSZ 256
#define D   512
#define KC  64
#define NKC 8
#define MT  128            /* a-rows per CTA */
#define NT  128            /* r-cols per CTA */
#define GROW 132
#define NEG (-1.0e30f)

// ---- smem layout (bytes) ----
#define W0_OFF 0
#define W1_OFF 16384
#define B0_OFF 32768
#define B1_OFF 49152       /* buffers end 65536 */
#define G_OFF  0           /* G[128][132] f32 = 67584, union with buffers */
#define MP_OFF   67584
#define RS_OFF   67600     /* rowS[128] */
#define RM_OFF   68112     /* rowMax[128] */
#define RED_OFF  68624     /* 32 floats */
#define SMEM_BYTES 68752

#define SW(o) ((o) ^ ((((unsigned)(o))>>3)&0x70u))

// ---- device scratch ----
__device__ __nv_bfloat16 g_Xb[BSZ*D];
__device__ __nv_bfloat16 g_Yb[BSZ*D];
__device__ float g_px2_m[BSZ*BSZ*2];   // [s][a][nh]
__device__ float g_px2_s[BSZ*BSZ*2];
__device__ float g_py2_m[BSZ*BSZ*2];   // [s][r][half]
__device__ float g_py2_s[BSZ*BSZ*2];
__device__ float g_pz_m[BSZ*4];        // [s][quadrant]
__device__ float g_pz_s[BSZ*4];
__device__ float g_line[BSZ];

static __device__ __forceinline__ uint32_t smem_u32(const void* p){
    uint32_t a;
    asm("{ .reg .u64 t; cvta.to.shared.u64 t, %1; cvt.u32.u64 %0, t; }" : "=r"(a) : "l"(p));
    return a;
}
#define LDSM_X4(r0,r1,r2,r3, addr) \
    asm volatile("ldmatrix.sync.aligned.m8n8.x4.shared.b16 {%0,%1,%2,%3}, [%4];" \
        : "=r"(r0),"=r"(r1),"=r"(r2),"=r"(r3) : "r"(addr))

__device__ __forceinline__ void lse_merge(float& M, float& S, float m2, float s2){
    if (m2 > M){ S = S * __expf(M - m2) + s2; M = m2; }
    else       { S = S + s2 * __expf(m2 - M); }
}

__global__ void conv_xy_kernel(const float* __restrict__ X, const float* __restrict__ Y){
    int i = blockIdx.x * blockDim.x + threadIdx.x;
    if (i < BSZ*D) g_Xb[i] = __float2bfloat16(X[i]);
    else           g_Yb[i - BSZ*D] = __float2bfloat16(Y[i - BSZ*D]);
}

// ---- pipeline helpers (256 threads) ----
static __device__ __forceinline__ void ldg_xb(int aBase, int k0, int tid, uint4 xr[4]){
    int row = tid >> 1, seg = tid & 1;
    const uint4* p = (const uint4*)(g_Xb + (size_t)(aBase + row)*D + k0 + seg*32);
    #pragma unroll
    for (int i = 0; i < 4; ++i) xr[i] = p[i];
}
static __device__ __forceinline__ void cpasync_y(uint32_t sb, int rBase, int k0,
                                                 int bufB, int tid){
    #pragma unroll
    for (int i = 0; i < 4; ++i){
        int gi = tid + 256*i;
        int row = gi >> 3, u = gi & 7;
        const void* src = (const void*)(g_Yb + (size_t)(rBase + row)*D + k0 + u*8);
        uint32_t dst = sb + bufB + SW((uint32_t)(row*128 + u*16));
        asm volatile("cp.async.cg.shared.global [%0], [%1], 16;"
            :: "r"(dst), "l"(__cvta_generic_to_global(src)) : "memory");
    }
    asm volatile("cp.async.commit_group;" ::: "memory");
}
static __device__ __forceinline__ void sts_w(const float* __restrict__ Z, char* smem,
                                             int s, int k0, int bufW, int tid,
                                             const uint4 xr[4]){
    int row = tid >> 1, seg = tid & 1;
    const float4* Zp = (const float4*)(Z + (size_t)s*D + k0 + seg*32);
    #pragma unroll
    for (int q = 0; q < 4; ++q){
        uint4 xv = xr[q];
        float4 z0 = Zp[2*q], z1 = Zp[2*q+1];
        float2 f0 = __bfloat1622float2(*(const __nv_bfloat162*)&xv.x);
        float2 f1 = __bfloat1622float2(*(const __nv_bfloat162*)&xv.y);
        float2 f2 = __bfloat1622float2(*(const __nv_bfloat162*)&xv.z);
        float2 f3 = __bfloat1622float2(*(const __nv_bfloat162*)&xv.w);
        __nv_bfloat162 r0 = __floats2bfloat162_rn(f0.x*z0.x, f0.y*z0.y);
        __nv_bfloat162 r1 = __floats2bfloat162_rn(f1.x*z0.z, f1.y*z0.w);
        __nv_bfloat162 r2 = __floats2bfloat162_rn(f2.x*z1.x, f2.y*z1.y);
        __nv_bfloat162 r3 = __floats2bfloat162_rn(f3.x*z1.z, f3.y*z1.w);
        uint32_t off = (uint32_t)(row*128 + seg*64 + q*16);
        *(uint4*)(smem + bufW + SW(off)) =
            make_uint4(*(uint32_t*)&r0, *(uint32_t*)&r1, *(uint32_t*)&r2, *(uint32_t*)&r3);
    }
}

__global__ void __launch_bounds__(256, 2)
symile_quad(const float* __restrict__ Z){
    extern __shared__ char smem[];
    const uint32_t sb = smem_u32(smem);
    const int tid = threadIdx.x, warp = tid >> 5, lane = tid & 31;
    const int s = blockIdx.x >> 2;
    const int half = (blockIdx.x >> 1) & 1, nh = blockIdx.x & 1;
    const int aBase = half * MT, rBase = nh * NT;
    const int wm = warp & 3, wn = warp >> 2;       // 4x2 warp grid: 32 x 64 tiles
    const int lrow = lane & 7, lsel = lane >> 3;
    const int g = lane >> 2, tg = lane & 3;

    float* G     = (float*)(smem + G_OFF);
    float* rowS  = (float*)(smem + RS_OFF);
    float* rowMx = (float*)(smem + RM_OFF);
    float* red   = (float*)(smem + RED_OFF);
    float* mpp   = (float*)(smem + MP_OFF);

    float c[2][8][4];
    #pragma unroll
    for (int mt = 0; mt < 2; ++mt)
        #pragma unroll
        for (int nt = 0; nt < 8; ++nt)
            #pragma unroll
            for (int i = 0; i < 4; ++i) c[mt][nt][i] = 0.f;

    // ---- prologue ----
    {
        uint4 xr[4];
        ldg_xb(aBase, 0, tid, xr);
        cpasync_y(sb, rBase, 0, B0_OFF, tid);
        sts_w(Z, smem, s, 0, W0_OFF, tid, xr);
        asm volatile("cp.async.wait_group 0;" ::: "memory");
        __syncthreads();
    }

    for (int kc = 0; kc < NKC; ++kc){
        const int b = kc & 1, nb = b ^ 1;
        uint4 xr[4];
        if (kc < NKC-1){
            ldg_xb(aBase, (kc+1)*KC, tid, xr);
            cpasync_y(sb, rBase, (kc+1)*KC, nb ? B1_OFF : B0_OFF, tid);
        }
        const uint32_t sA = sb + (b ? W1_OFF : W0_OFF);
        const uint32_t sB = sb + (b ? B1_OFF : B0_OFF);
        #pragma unroll
        for (int ks = 0; ks < 4; ++ks){
            unsigned a[2][4], bb[8][2];
            {
                uint32_t arow = (uint32_t)(wm*32 + (lsel & 1)*8 + lrow);
                uint32_t acol = (uint32_t)(ks*32 + (lsel >> 1)*16);
                #pragma unroll
                for (int mt = 0; mt < 2; ++mt){
                    uint32_t o = (arow + mt*16)*128 + acol;
                    LDSM_X4(a[mt][0], a[mt][1], a[mt][2], a[mt][3], sA + SW(o));
                }
            }
            {
                uint32_t brow = (uint32_t)(wn*64 + (lsel >> 1)*8 + lrow);
                uint32_t bcol = (uint32_t)(ks*32 + (lsel & 1)*16);
                #pragma unroll
                for (int p = 0; p < 4; ++p){
                    uint32_t o = (brow + p*16)*128 + bcol;
                    LDSM_X4(bb[2*p][0], bb[2*p][1], bb[2*p+1][0], bb[2*p+1][1], sB + SW(o));
                }
            }
            #pragma unroll
            for (int mt = 0; mt < 2; ++mt)
                #pragma unroll
                for (int nt = 0; nt < 8; ++nt)
                    asm volatile(
                      "mma.sync.aligned.m16n8k16.row.col.f32.bf16.bf16.f32 "
                      "{%0,%1,%2,%3}, {%4,%5,%6,%7}, {%8,%9}, {%0,%1,%2,%3};\n"
                      : "+f"(c[mt][nt][0]), "+f"(c[mt][nt][1]),
                        "+f"(c[mt][nt][2]), "+f"(c[mt][nt][3])
                      : "r"(a[mt][0]), "r"(a[mt][1]), "r"(a[mt][2]), "r"(a[mt][3]),
                        "r"(bb[nt][0]), "r"(bb[nt][1]));
        }
        if (kc < NKC-1){
            sts_w(Z, smem, s, (kc+1)*KC, nb ? W1_OFF : W0_OFF, tid, xr);
            asm volatile("cp.async.wait_group 0;" ::: "memory");
        }
        __syncthreads();
    }

    // ---- spill G[128][132] (float2 stores) ----
    #pragma unroll
    for (int mt = 0; mt < 2; ++mt)
        #pragma unroll
        for (int nt = 0; nt < 8; ++nt){
            int row = wm*32 + mt*16 + g;
            int col = wn*64 + nt*8 + tg*2;
            *(float2*)&G[row*GROW + col]     = make_float2(c[mt][nt][0], c[mt][nt][1]);
            *(float2*)&G[(row+8)*GROW + col] = make_float2(c[mt][nt][2], c[mt][nt][3]);
        }
    __syncthreads();

    const int row = tid >> 1, part = tid & 1;
    float* Gr = G + row*GROW + part*64;

    // ---- pass 1: plane max ----
    {
        float m = NEG;
        #pragma unroll
        for (int q = 0; q < 16; ++q){
            float4 v = *(const float4*)(Gr + q*4);
            m = fmaxf(m, fmaxf(fmaxf(v.x, v.y), fmaxf(v.z, v.w)));
        }
        m = fmaxf(m, __shfl_xor_sync(0xffffffffu, m, 1));
        if (part == 0) rowMx[row] = m;
    }
    __syncthreads();
    if (warp < 4){
        float m = rowMx[warp*32 + lane];
        #pragma unroll
        for (int off = 16; off > 0; off >>= 1)
            m = fmaxf(m, __shfl_xor_sync(0xffffffffu, m, off));
        if (lane == 0) red[warp] = m;
    }
    __syncthreads();
    if (tid == 0)
        mpp[0] = fmaxf(fmaxf(red[0], red[1]), fmaxf(red[2], red[3]));
    __syncthreads();
    const float mp = mpp[0];

    // ---- pass 2: e = exp(G - mp), writeback, row sums ----
    {
        float sum = 0.f;
        #pragma unroll
        for (int q = 0; q < 16; ++q){
            float4 v = *(const float4*)(Gr + q*4);
            v.x = __expf(v.x - mp); v.y = __expf(v.y - mp);
            v.z = __expf(v.z - mp); v.w = __expf(v.w - mp);
            *(float4*)(Gr + q*4) = v;
            sum += (v.x + v.y) + (v.z + v.w);
        }
        sum += __shfl_xor_sync(0xffffffffu, sum, 1);
        if (part == 0){
            rowS[row] = sum;
            int idx = (s*BSZ + aBase + row)*2 + nh;
            g_px2_m[idx] = mp; g_px2_s[idx] = sum;
        }
    }
    __syncthreads();

    // ---- pass 3: column sums (pure adds) + plane sum ----
    {
        const int col = tid >> 1;
        const float* Gc = G + part*64*GROW + col;
        float sum = 0.f;
        #pragma unroll 8
        for (int rr = 0; rr < 64; ++rr) sum += Gc[rr*GROW];
        sum += __shfl_xor_sync(0xffffffffu, sum, 1);
        if (part == 0){
            int idx = (s*BSZ + rBase + col)*2 + half;
            g_py2_m[idx] = mp; g_py2_s[idx] = sum;
        }
    }
    if (warp < 4){
        float v = rowS[warp*32 + lane];
        #pragma unroll
        for (int off = 16; off > 0; off >>= 1)
            v += __shfl_xor_sync(0xffffffffu, v, off);
        if (lane == 0) red[8 + warp] = v;
    }
    __syncthreads();
    if (tid == 0){
        int idx = s*4 + half*2 + nh;
        g_pz_m[idx] = mp;
        g_pz_s[idx] = (red[8] + red[9]) + (red[10] + red[11]);
    }
}

__global__ void finalize1(const float* __restrict__ X, const float* __restrict__ Y,
                          const float* __restrict__ Z){
    __shared__ float wred[8*5];
    const int t = blockIdx.x, si = threadIdx.x;
    const int warp = si >> 5, lane = si & 31;

    float Mx = NEG, Sx = 0.f, My = NEG, Sy = 0.f;
    {
        int b = (si*BSZ + t)*2;
        lse_merge(Mx, Sx, g_px2_m[b],   g_px2_s[b]);
        lse_merge(Mx, Sx, g_px2_m[b+1], g_px2_s[b+1]);
        lse_merge(My, Sy, g_py2_m[b],   g_py2_s[b]);
        lse_merge(My, Sy, g_py2_m[b+1], g_py2_s[b+1]);
    }
    float dg = X[t*D + 2*si]   * Y[t*D + 2*si]   * Z[t*D + 2*si]
             + X[t*D + 2*si+1] * Y[t*D + 2*si+1] * Z[t*D + 2*si+1];

    #pragma unroll
    for (int off = 16; off > 0; off >>= 1){
        float m2 = __shfl_xor_sync(0xffffffffu, Mx, off);
        float s2 = __shfl_xor_sync(0xffffffffu, Sx, off);
        lse_merge(Mx, Sx, m2, s2);
        m2 = __shfl_xor_sync(0xffffffffu, My, off);
        s2 = __shfl_xor_sync(0xffffffffu, Sy, off);
        lse_merge(My, Sy, m2, s2);
        dg += __shfl_xor_sync(0xffffffffu, dg, off);
    }
    if (lane == 0){
        wred[warp*5+0] = Mx; wred[warp*5+1] = Sx;
        wred[warp*5+2] = My; wred[warp*5+3] = Sy;
        wred[warp*5+4] = dg;
    }
    __syncthreads();
    if (si == 0){
        float MX = NEG, SX = 0.f, MY = NEG, SY = 0.f, DG = 0.f;
        #pragma unroll
        for (int w = 0; w < 8; ++w){
            lse_merge(MX, SX, wred[w*5+0], wred[w*5+1]);
            lse_merge(MY, SY, wred[w*5+2], wred[w*5+3]);
            DG += wred[w*5+4];
        }
        float MZ = NEG, SZ = 0.f;
        #pragma unroll
        for (int q = 0; q < 4; ++q)
            lse_merge(MZ, SZ, g_pz_m[t*4+q], g_pz_s[t*4+q]);
        g_line[t] = (MX + logf(SX)) + (MY + logf(SY)) + (MZ + logf(SZ)) - 3.f*DG;
    }
}

__global__ void finalize2(float* __restrict__ out){
    __shared__ float red[BSZ];
    int t = threadIdx.x;
    red[t] = g_line[t];
    __syncthreads();
    for (int off = 128; off > 0; off >>= 1){
        if (t < off) red[t] += red[t + off];
        __syncthreads();
    }
    if (t == 0) out[0] = red[0] / 768.f;
}

extern "C" void kernel_launch(void* const* d_in, const int* in_sizes, int n_in,
                              void* d_out, int out_size){
    const float* X = (const float*)d_in[0];
    const float* Y = (const float*)d_in[1];
    const float* Z = (const float*)d_in[2];
    float* out = (float*)d_out;

    cudaFuncSetAttribute(symile_quad, cudaFuncAttributeMaxDynamicSharedMemorySize, SMEM_BYTES);

    conv_xy_kernel<<<(2*BSZ*D)/256, 256>>>(X, Y);
    symile_quad<<<BSZ*4, 256, SMEM_BYTES>>>(Z);
    finalize1<<<BSZ, 256>>>(X, Y, Z);
    finalize2<<<1, BSZ>>>(out);
}

// round 10
// speedup vs baseline: 2.3939x; 1.7608x over previous
#include <cuda_runtime.h>
#include <cuda_bf16.h>
#include <math.h>
#include <stdint.h>

#define BSZ 256
#define D   512
#define KC  64
#define NKC 8
#define MT  128
#define NT  128
#define GROW 132
#define NEG (-1.0e30f)

// ---- mainloop smem: 3-stage ring, each stage = W(16KB) + Y(16KB) ----
#define STAGE_BYTES 32768
#define RING_OFF(st) ((st)*STAGE_BYTES)
#define YOFS 16384
#define G_OFF  0                 /* G[128][132] f32 = 67584, union with ring */
#define MP_OFF   98304
#define RS_OFF   98320
#define RM_OFF   98832
#define RED_OFF  99344
#define SMEM_BYTES 99488

#define SW(o) ((o) ^ ((((unsigned)(o))>>3)&0x70u))

// ---- device scratch ----
__device__ __nv_bfloat16 g_W[BSZ*BSZ*D];   // 64 MiB: W[s][a][d] = x[a,d]*z[s,d]
__device__ __nv_bfloat16 g_Yb[BSZ*D];
__device__ float g_px2_m[BSZ*BSZ*2];
__device__ float g_px2_s[BSZ*BSZ*2];
__device__ float g_py2_m[BSZ*BSZ*2];
__device__ float g_py2_s[BSZ*BSZ*2];
__device__ float g_pz_m[BSZ*4];
__device__ float g_pz_s[BSZ*4];
__device__ float g_line[BSZ];

static __device__ __forceinline__ uint32_t smem_u32(const void* p){
    uint32_t a;
    asm("{ .reg .u64 t; cvta.to.shared.u64 t, %1; cvt.u32.u64 %0, t; }" : "=r"(a) : "l"(p));
    return a;
}
#define LDSM_X4(r0,r1,r2,r3, addr) \
    asm volatile("ldmatrix.sync.aligned.m8n8.x4.shared.b16 {%0,%1,%2,%3}, [%4];" \
        : "=r"(r0),"=r"(r1),"=r"(r2),"=r"(r3) : "r"(addr))

__device__ __forceinline__ void lse_merge(float& M, float& S, float m2, float s2){
    if (m2 > M){ S = S * __expf(M - m2) + s2; M = m2; }
    else       { S = S + s2 * __expf(m2 - M); }
}

// ============ prep: W[s][a][:] = X[a,:]*Z[s,:] (tiled), plus Y->bf16 ============
// blocks [0,256): W tiles (16 s-rows x 16 a-rows, full D). blocks [256,320): Y conv.
__global__ void __launch_bounds__(256, 2)
prep_kernel(const float* __restrict__ X, const float* __restrict__ Y,
            const float* __restrict__ Z){
    extern __shared__ float sm[];           // Xs[16][512] + Zs[16][512]
    float* Xs = sm;
    float* Zs = sm + 16*512;
    const int tid = threadIdx.x, bid = blockIdx.x;
    if (bid < 256){
        const int sblk = bid >> 4, ablk = bid & 15;
        #pragma unroll
        for (int j = 0; j < 8; ++j){
            int idx = tid + 256*j;          // float4 granule id (2048 per tile)
            int row = idx >> 7, q = idx & 127;   // 128 float4 per 512-float row
            ((float4*)Xs)[row*128 + q] = *(const float4*)(X + (size_t)(ablk*16+row)*D + q*4);
            ((float4*)Zs)[row*128 + q] = *(const float4*)(Z + (size_t)(sblk*16+row)*D + q*4);
        }
        __syncthreads();
        #pragma unroll
        for (int j = 0; j < 4; ++j){
            int gid = tid + 256*j;          // 8-elem granule within 16x512 tile
            int row = gid >> 6, c8 = gid & 63;
            const float4 xv0 = ((const float4*)Xs)[row*128 + c8*2];
            const float4 xv1 = ((const float4*)Xs)[row*128 + c8*2 + 1];
            #pragma unroll
            for (int s = 0; s < 16; ++s){
                float4 zv0 = ((const float4*)Zs)[s*128 + c8*2];
                float4 zv1 = ((const float4*)Zs)[s*128 + c8*2 + 1];
                __nv_bfloat162 r0 = __floats2bfloat162_rn(xv0.x*zv0.x, xv0.y*zv0.y);
                __nv_bfloat162 r1 = __floats2bfloat162_rn(xv0.z*zv0.z, xv0.w*zv0.w);
                __nv_bfloat162 r2 = __floats2bfloat162_rn(xv1.x*zv1.x, xv1.y*zv1.y);
                __nv_bfloat162 r3 = __floats2bfloat162_rn(xv1.z*zv1.z, xv1.w*zv1.w);
                size_t o = ((size_t)(sblk*16+s)*BSZ + ablk*16 + row)*D + c8*8;
                *(uint4*)(g_W + o) = make_uint4(*(uint32_t*)&r0, *(uint32_t*)&r1,
                                                *(uint32_t*)&r2, *(uint32_t*)&r3);
            }
        }
    } else {
        int base = ((bid - 256)*256 + tid)*8;
        float4 v0 = *(const float4*)(Y + base);
        float4 v1 = *(const float4*)(Y + base + 4);
        __nv_bfloat162 r0 = __floats2bfloat162_rn(v0.x, v0.y);
        __nv_bfloat162 r1 = __floats2bfloat162_rn(v0.z, v0.w);
        __nv_bfloat162 r2 = __floats2bfloat162_rn(v1.x, v1.y);
        __nv_bfloat162 r3 = __floats2bfloat162_rn(v1.z, v1.w);
        *(uint4*)(g_Yb + base) = make_uint4(*(uint32_t*)&r0, *(uint32_t*)&r1,
                                            *(uint32_t*)&r2, *(uint32_t*)&r3);
    }
}

// ============ main: one 128x128 quadrant per CTA ============
static __device__ __forceinline__ void issue_chunk(uint32_t sb, int stage,
                                                   const __nv_bfloat16* wRow0,
                                                   const __nv_bfloat16* yRow0,
                                                   int k0, int tid){
    const uint32_t base = sb + RING_OFF(stage);
    #pragma unroll
    for (int i = 0; i < 4; ++i){
        int gi = tid + 256*i;
        int row = gi >> 3, u = gi & 7;
        uint32_t so = SW((uint32_t)(row*128 + u*16));
        asm volatile("cp.async.cg.shared.global [%0], [%1], 16;"
            :: "r"(base + so),
               "l"(__cvta_generic_to_global(wRow0 + (size_t)row*D + k0 + u*8)) : "memory");
        asm volatile("cp.async.cg.shared.global [%0], [%1], 16;"
            :: "r"(base + YOFS + so),
               "l"(__cvta_generic_to_global(yRow0 + (size_t)row*D + k0 + u*8)) : "memory");
    }
    asm volatile("cp.async.commit_group;" ::: "memory");
}

__global__ void __launch_bounds__(256, 2)
symile_quad(const float* __restrict__ Zunused){
    extern __shared__ char smem[];
    const uint32_t sb = smem_u32(smem);
    const int tid = threadIdx.x, warp = tid >> 5, lane = tid & 31;
    const int s = blockIdx.x >> 2;
    const int half = (blockIdx.x >> 1) & 1, nh = blockIdx.x & 1;
    const int aBase = half * MT, rBase = nh * NT;
    const int wm = warp & 3, wn = warp >> 2;
    const int lrow = lane & 7, lsel = lane >> 3;
    const int g = lane >> 2, tg = lane & 3;

    const __nv_bfloat16* wRow0 = g_W + ((size_t)s*BSZ + aBase)*D;
    const __nv_bfloat16* yRow0 = g_Yb + (size_t)rBase*D;

    float* G     = (float*)(smem + G_OFF);
    float* rowS  = (float*)(smem + RS_OFF);
    float* rowMx = (float*)(smem + RM_OFF);
    float* red   = (float*)(smem + RED_OFF);
    float* mpp   = (float*)(smem + MP_OFF);

    float c[2][8][4];
    #pragma unroll
    for (int mt = 0; mt < 2; ++mt)
        #pragma unroll
        for (int nt = 0; nt < 8; ++nt)
            #pragma unroll
            for (int i = 0; i < 4; ++i) c[mt][nt][i] = 0.f;

    issue_chunk(sb, 0, wRow0, yRow0, 0, tid);
    issue_chunk(sb, 1, wRow0, yRow0, KC, tid);

    for (int kc = 0; kc < NKC; ++kc){
        if (kc + 2 < NKC)
            issue_chunk(sb, (kc+2)%3, wRow0, yRow0, (kc+2)*KC, tid);
        if (kc < NKC-2)       asm volatile("cp.async.wait_group 2;" ::: "memory");
        else if (kc == NKC-2) asm volatile("cp.async.wait_group 1;" ::: "memory");
        else                  asm volatile("cp.async.wait_group 0;" ::: "memory");
        __syncthreads();

        const uint32_t sA = sb + RING_OFF(kc%3);
        const uint32_t sB = sA + YOFS;
        #pragma unroll
        for (int ks = 0; ks < 4; ++ks){
            unsigned a[2][4], bb[8][2];
            {
                uint32_t arow = (uint32_t)(wm*32 + (lsel & 1)*8 + lrow);
                uint32_t acol = (uint32_t)(ks*32 + (lsel >> 1)*16);
                #pragma unroll
                for (int mt = 0; mt < 2; ++mt){
                    uint32_t o = (arow + mt*16)*128 + acol;
                    LDSM_X4(a[mt][0], a[mt][1], a[mt][2], a[mt][3], sA + SW(o));
                }
            }
            {
                uint32_t brow = (uint32_t)(wn*64 + (lsel >> 1)*8 + lrow);
                uint32_t bcol = (uint32_t)(ks*32 + (lsel & 1)*16);
                #pragma unroll
                for (int p = 0; p < 4; ++p){
                    uint32_t o = (brow + p*16)*128 + bcol;
                    LDSM_X4(bb[2*p][0], bb[2*p][1], bb[2*p+1][0], bb[2*p+1][1], sB + SW(o));
                }
            }
            #pragma unroll
            for (int mt = 0; mt < 2; ++mt)
                #pragma unroll
                for (int nt = 0; nt < 8; ++nt)
                    asm volatile(
                      "mma.sync.aligned.m16n8k16.row.col.f32.bf16.bf16.f32 "
                      "{%0,%1,%2,%3}, {%4,%5,%6,%7}, {%8,%9}, {%0,%1,%2,%3};\n"
                      : "+f"(c[mt][nt][0]), "+f"(c[mt][nt][1]),
                        "+f"(c[mt][nt][2]), "+f"(c[mt][nt][3])
                      : "r"(a[mt][0]), "r"(a[mt][1]), "r"(a[mt][2]), "r"(a[mt][3]),
                        "r"(bb[nt][0]), "r"(bb[nt][1]));
        }
        __syncthreads();
    }

    // ---- spill G ----
    #pragma unroll
    for (int mt = 0; mt < 2; ++mt)
        #pragma unroll
        for (int nt = 0; nt < 8; ++nt){
            int row = wm*32 + mt*16 + g;
            int col = wn*64 + nt*8 + tg*2;
            *(float2*)&G[row*GROW + col]     = make_float2(c[mt][nt][0], c[mt][nt][1]);
            *(float2*)&G[(row+8)*GROW + col] = make_float2(c[mt][nt][2], c[mt][nt][3]);
        }
    __syncthreads();

    const int row = tid >> 1, part = tid & 1;
    float* Gr = G + row*GROW + part*64;

    // pass 1: plane max
    {
        float m = NEG;
        #pragma unroll
        for (int q = 0; q < 16; ++q){
            float4 v = *(const float4*)(Gr + q*4);
            m = fmaxf(m, fmaxf(fmaxf(v.x, v.y), fmaxf(v.z, v.w)));
        }
        m = fmaxf(m, __shfl_xor_sync(0xffffffffu, m, 1));
        if (part == 0) rowMx[row] = m;
    }
    __syncthreads();
    if (warp < 4){
        float m = rowMx[warp*32 + lane];
        #pragma unroll
        for (int off = 16; off > 0; off >>= 1)
            m = fmaxf(m, __shfl_xor_sync(0xffffffffu, m, off));
        if (lane == 0) red[warp] = m;
    }
    __syncthreads();
    if (tid == 0)
        mpp[0] = fmaxf(fmaxf(red[0], red[1]), fmaxf(red[2], red[3]));
    __syncthreads();
    const float mp = mpp[0];

    // pass 2: exp writeback + row sums
    {
        float sum = 0.f;
        #pragma unroll
        for (int q = 0; q < 16; ++q){
            float4 v = *(const float4*)(Gr + q*4);
            v.x = __expf(v.x - mp); v.y = __expf(v.y - mp);
            v.z = __expf(v.z - mp); v.w = __expf(v.w - mp);
            *(float4*)(Gr + q*4) = v;
            sum += (v.x + v.y) + (v.z + v.w);
        }
        sum += __shfl_xor_sync(0xffffffffu, sum, 1);
        if (part == 0){
            rowS[row] = sum;
            int idx = (s*BSZ + aBase + row)*2 + nh;
            g_px2_m[idx] = mp; g_px2_s[idx] = sum;
        }
    }
    __syncthreads();

    // pass 3: column sums + plane sum
    {
        const int col = tid >> 1;
        const float* Gc = G + part*64*GROW + col;
        float sum = 0.f;
        #pragma unroll 8
        for (int rr = 0; rr < 64; ++rr) sum += Gc[rr*GROW];
        sum += __shfl_xor_sync(0xffffffffu, sum, 1);
        if (part == 0){
            int idx = (s*BSZ + rBase + col)*2 + half;
            g_py2_m[idx] = mp; g_py2_s[idx] = sum;
        }
    }
    if (warp < 4){
        float v = rowS[warp*32 + lane];
        #pragma unroll
        for (int off = 16; off > 0; off >>= 1)
            v += __shfl_xor_sync(0xffffffffu, v, off);
        if (lane == 0) red[8 + warp] = v;
    }
    __syncthreads();
    if (tid == 0){
        int idx = s*4 + half*2 + nh;
        g_pz_m[idx] = mp;
        g_pz_s[idx] = (red[8] + red[9]) + (red[10] + red[11]);
    }
}

__global__ void finalize1(const float* __restrict__ X, const float* __restrict__ Y,
                          const float* __restrict__ Z){
    __shared__ float wred[8*5];
    const int t = blockIdx.x, si = threadIdx.x;
    const int warp = si >> 5, lane = si & 31;

    float Mx = NEG, Sx = 0.f, My = NEG, Sy = 0.f;
    {
        int b = (si*BSZ + t)*2;
        lse_merge(Mx, Sx, g_px2_m[b],   g_px2_s[b]);
        lse_merge(Mx, Sx, g_px2_m[b+1], g_px2_s[b+1]);
        lse_merge(My, Sy, g_py2_m[b],   g_py2_s[b]);
        lse_merge(My, Sy, g_py2_m[b+1], g_py2_s[b+1]);
    }
    float dg = X[t*D + 2*si]   * Y[t*D + 2*si]   * Z[t*D + 2*si]
             + X[t*D + 2*si+1] * Y[t*D + 2*si+1] * Z[t*D + 2*si+1];

    #pragma unroll
    for (int off = 16; off > 0; off >>= 1){
        float m2 = __shfl_xor_sync(0xffffffffu, Mx, off);
        float s2 = __shfl_xor_sync(0xffffffffu, Sx, off);
        lse_merge(Mx, Sx, m2, s2);
        m2 = __shfl_xor_sync(0xffffffffu, My, off);
        s2 = __shfl_xor_sync(0xffffffffu, Sy, off);
        lse_merge(My, Sy, m2, s2);
        dg += __shfl_xor_sync(0xffffffffu, dg, off);
    }
    if (lane == 0){
        wred[warp*5+0] = Mx; wred[warp*5+1] = Sx;
        wred[warp*5+2] = My; wred[warp*5+3] = Sy;
        wred[warp*5+4] = dg;
    }
    __syncthreads();
    if (si == 0){
        float MX = NEG, SX = 0.f, MY = NEG, SY = 0.f, DG = 0.f;
        #pragma unroll
        for (int w = 0; w < 8; ++w){
            lse_merge(MX, SX, wred[w*5+0], wred[w*5+1]);
            lse_merge(MY, SY, wred[w*5+2], wred[w*5+3]);
            DG += wred[w*5+4];
        }
        float MZ = NEG, SZ = 0.f;
        #pragma unroll
        for (int q = 0; q < 4; ++q)
            lse_merge(MZ, SZ, g_pz_m[t*4+q], g_pz_s[t*4+q]);
        g_line[t] = (MX + logf(SX)) + (MY + logf(SY)) + (MZ + logf(SZ)) - 3.f*DG;
    }
}

__global__ void finalize2(float* __restrict__ out){
    int lane = threadIdx.x;
    float v = 0.f;
    #pragma unroll
    for (int j = 0; j < 8; ++j) v += g_line[lane + j*32];
    #pragma unroll
    for (int off = 16; off > 0; off >>= 1)
        v += __shfl_xor_sync(0xffffffffu, v, off);
    if (lane == 0) out[0] = v / 768.f;
}

extern "C" void kernel_launch(void* const* d_in, const int* in_sizes, int n_in,
                              void* d_out, int out_size){
    const float* X = (const float*)d_in[0];
    const float* Y = (const float*)d_in[1];
    const float* Z = (const float*)d_in[2];
    float* out = (float*)d_out;

    cudaFuncSetAttribute(symile_quad, cudaFuncAttributeMaxDynamicSharedMemorySize, SMEM_BYTES);
    cudaFuncSetAttribute(prep_kernel, cudaFuncAttributeMaxDynamicSharedMemorySize, 65536);

    prep_kernel<<<320, 256, 65536>>>(X, Y, Z);
    symile_quad<<<BSZ*4, 256, SMEM_BYTES>>>(Z);
    finalize1<<<BSZ, 256>>>(X, Y, Z);
    finalize2<<<1, 32>>>(out);
}

// round 11
// speedup vs baseline: 2.5130x; 1.0497x over previous
#include <cuda_runtime.h>
#include <cuda_bf16.h>
#include <math.h>
#include <stdint.h>

#define BSZ 256
#define D   512
#define KC  64
#define NKC 8
#define MT  128
#define NT  128
#define GROW 132
#define NEG (-1.0e30f)

// ---- mainloop smem: 3-stage ring, each stage = W(16KB) + Y(16KB) ----
#define STAGE_BYTES 32768
#define RING_OFF(st) ((st)*STAGE_BYTES)
#define YOFS 16384
#define G_OFF  0                 /* G[128][132] f32 = 67584, union with ring */
#define MP_OFF   98304
#define RS_OFF   98320
#define RED_OFF  98832
#define SMEM_BYTES 98976

#define SW(o) ((o) ^ ((((unsigned)(o))>>3)&0x70u))

// ---- device scratch ----
__device__ __nv_bfloat16 g_W[BSZ*BSZ*D];   // 64 MiB: W[s][a][d] = x[a,d]*z[s,d]
__device__ __nv_bfloat16 g_Yb[BSZ*D];
__device__ float g_px2_m[BSZ*BSZ*2];
__device__ float g_px2_s[BSZ*BSZ*2];
__device__ float g_py2_m[BSZ*BSZ*2];
__device__ float g_py2_s[BSZ*BSZ*2];
__device__ float g_pz_m[BSZ*4];
__device__ float g_pz_s[BSZ*4];
__device__ float g_line[BSZ];
__device__ int   g_ctr;                    // last-block counter (self-resetting)

static __device__ __forceinline__ uint32_t smem_u32(const void* p){
    uint32_t a;
    asm("{ .reg .u64 t; cvta.to.shared.u64 t, %1; cvt.u32.u64 %0, t; }" : "=r"(a) : "l"(p));
    return a;
}
#define LDSM_X4(r0,r1,r2,r3, addr) \
    asm volatile("ldmatrix.sync.aligned.m8n8.x4.shared.b16 {%0,%1,%2,%3}, [%4];" \
        : "=r"(r0),"=r"(r1),"=r"(r2),"=r"(r3) : "r"(addr))

__device__ __forceinline__ void lse_merge(float& M, float& S, float m2, float s2){
    if (m2 > M){ S = S * __expf(M - m2) + s2; M = m2; }
    else       { S = S + s2 * __expf(m2 - M); }
}

// ============ prep: W[s][a][:] = X[a,:]*Z[s,:] (tiled), plus Y->bf16 ============
__global__ void __launch_bounds__(256, 2)
prep_kernel(const float* __restrict__ X, const float* __restrict__ Y,
            const float* __restrict__ Z){
    extern __shared__ float sm[];           // Xs[16][512] + Zs[16][512]
    float* Xs = sm;
    float* Zs = sm + 16*512;
    const int tid = threadIdx.x, bid = blockIdx.x;
    if (bid < 256){
        const int sblk = bid >> 4, ablk = bid & 15;
        #pragma unroll
        for (int j = 0; j < 8; ++j){
            int idx = tid + 256*j;               // float4 granule (2048/tile)
            int row = idx >> 7, q = idx & 127;   // 128 float4 per row
            ((float4*)Xs)[row*128 + q] = *(const float4*)(X + (size_t)(ablk*16+row)*D + q*4);
            ((float4*)Zs)[row*128 + q] = *(const float4*)(Z + (size_t)(sblk*16+row)*D + q*4);
        }
        __syncthreads();
        #pragma unroll
        for (int j = 0; j < 4; ++j){
            int gid = tid + 256*j;
            int row = gid >> 6, c8 = gid & 63;
            const float4 xv0 = ((const float4*)Xs)[row*128 + c8*2];
            const float4 xv1 = ((const float4*)Xs)[row*128 + c8*2 + 1];
            #pragma unroll
            for (int s = 0; s < 16; ++s){
                float4 zv0 = ((const float4*)Zs)[s*128 + c8*2];
                float4 zv1 = ((const float4*)Zs)[s*128 + c8*2 + 1];
                __nv_bfloat162 r0 = __floats2bfloat162_rn(xv0.x*zv0.x, xv0.y*zv0.y);
                __nv_bfloat162 r1 = __floats2bfloat162_rn(xv0.z*zv0.z, xv0.w*zv0.w);
                __nv_bfloat162 r2 = __floats2bfloat162_rn(xv1.x*zv1.x, xv1.y*zv1.y);
                __nv_bfloat162 r3 = __floats2bfloat162_rn(xv1.z*zv1.z, xv1.w*zv1.w);
                size_t o = ((size_t)(sblk*16+s)*BSZ + ablk*16 + row)*D + c8*8;
                *(uint4*)(g_W + o) = make_uint4(*(uint32_t*)&r0, *(uint32_t*)&r1,
                                                *(uint32_t*)&r2, *(uint32_t*)&r3);
            }
        }
    } else {
        int base = ((bid - 256)*256 + tid)*8;
        float4 v0 = *(const float4*)(Y + base);
        float4 v1 = *(const float4*)(Y + base + 4);
        __nv_bfloat162 r0 = __floats2bfloat162_rn(v0.x, v0.y);
        __nv_bfloat162 r1 = __floats2bfloat162_rn(v0.z, v0.w);
        __nv_bfloat162 r2 = __floats2bfloat162_rn(v1.x, v1.y);
        __nv_bfloat162 r3 = __floats2bfloat162_rn(v1.z, v1.w);
        *(uint4*)(g_Yb + base) = make_uint4(*(uint32_t*)&r0, *(uint32_t*)&r1,
                                            *(uint32_t*)&r2, *(uint32_t*)&r3);
    }
}

// ============ main: one 128x128 quadrant per CTA ============
static __device__ __forceinline__ void issue_chunk(uint32_t sb, int stage,
                                                   const __nv_bfloat16* wRow0,
                                                   const __nv_bfloat16* yRow0,
                                                   int k0, int tid){
    const uint32_t base = sb + RING_OFF(stage);
    #pragma unroll
    for (int i = 0; i < 4; ++i){
        int gi = tid + 256*i;
        int row = gi >> 3, u = gi & 7;
        uint32_t so = SW((uint32_t)(row*128 + u*16));
        asm volatile("cp.async.cg.shared.global [%0], [%1], 16;"
            :: "r"(base + so),
               "l"(__cvta_generic_to_global(wRow0 + (size_t)row*D + k0 + u*8)) : "memory");
        asm volatile("cp.async.cg.shared.global [%0], [%1], 16;"
            :: "r"(base + YOFS + so),
               "l"(__cvta_generic_to_global(yRow0 + (size_t)row*D + k0 + u*8)) : "memory");
    }
    asm volatile("cp.async.commit_group;" ::: "memory");
}

__global__ void __launch_bounds__(256, 2)
symile_quad(){
    extern __shared__ char smem[];
    const uint32_t sb = smem_u32(smem);
    const int tid = threadIdx.x, warp = tid >> 5, lane = tid & 31;
    const int s = blockIdx.x >> 2;
    const int half = (blockIdx.x >> 1) & 1, nh = blockIdx.x & 1;
    const int aBase = half * MT, rBase = nh * NT;
    const int wm = warp & 3, wn = warp >> 2;
    const int lrow = lane & 7, lsel = lane >> 3;
    const int g = lane >> 2, tg = lane & 3;

    const __nv_bfloat16* wRow0 = g_W + ((size_t)s*BSZ + aBase)*D;
    const __nv_bfloat16* yRow0 = g_Yb + (size_t)rBase*D;

    float* G     = (float*)(smem + G_OFF);
    float* rowS  = (float*)(smem + RS_OFF);
    float* red   = (float*)(smem + RED_OFF);
    float* mpp   = (float*)(smem + MP_OFF);

    float c[2][8][4];
    #pragma unroll
    for (int mt = 0; mt < 2; ++mt)
        #pragma unroll
        for (int nt = 0; nt < 8; ++nt)
            #pragma unroll
            for (int i = 0; i < 4; ++i) c[mt][nt][i] = 0.f;

    issue_chunk(sb, 0, wRow0, yRow0, 0, tid);
    issue_chunk(sb, 1, wRow0, yRow0, KC, tid);

    for (int kc = 0; kc < NKC; ++kc){
        if (kc + 2 < NKC)
            issue_chunk(sb, (kc+2)%3, wRow0, yRow0, (kc+2)*KC, tid);
        if (kc < NKC-2)       asm volatile("cp.async.wait_group 2;" ::: "memory");
        else if (kc == NKC-2) asm volatile("cp.async.wait_group 1;" ::: "memory");
        else                  asm volatile("cp.async.wait_group 0;" ::: "memory");
        __syncthreads();

        const uint32_t sA = sb + RING_OFF(kc%3);
        const uint32_t sB = sA + YOFS;
        #pragma unroll
        for (int ks = 0; ks < 4; ++ks){
            unsigned a[2][4], bb[8][2];
            {
                uint32_t arow = (uint32_t)(wm*32 + (lsel & 1)*8 + lrow);
                uint32_t acol = (uint32_t)(ks*32 + (lsel >> 1)*16);
                #pragma unroll
                for (int mt = 0; mt < 2; ++mt){
                    uint32_t o = (arow + mt*16)*128 + acol;
                    LDSM_X4(a[mt][0], a[mt][1], a[mt][2], a[mt][3], sA + SW(o));
                }
            }
            {
                uint32_t brow = (uint32_t)(wn*64 + (lsel >> 1)*8 + lrow);
                uint32_t bcol = (uint32_t)(ks*32 + (lsel & 1)*16);
                #pragma unroll
                for (int p = 0; p < 4; ++p){
                    uint32_t o = (brow + p*16)*128 + bcol;
                    LDSM_X4(bb[2*p][0], bb[2*p][1], bb[2*p+1][0], bb[2*p+1][1], sB + SW(o));
                }
            }
            #pragma unroll
            for (int mt = 0; mt < 2; ++mt)
                #pragma unroll
                for (int nt = 0; nt < 8; ++nt)
                    asm volatile(
                      "mma.sync.aligned.m16n8k16.row.col.f32.bf16.bf16.f32 "
                      "{%0,%1,%2,%3}, {%4,%5,%6,%7}, {%8,%9}, {%0,%1,%2,%3};\n"
                      : "+f"(c[mt][nt][0]), "+f"(c[mt][nt][1]),
                        "+f"(c[mt][nt][2]), "+f"(c[mt][nt][3])
                      : "r"(a[mt][0]), "r"(a[mt][1]), "r"(a[mt][2]), "r"(a[mt][3]),
                        "r"(bb[nt][0]), "r"(bb[nt][1]));
        }
        __syncthreads();
    }

    // ---- plane max from accumulator REGISTERS (no G pass) ----
    {
        float m = NEG;
        #pragma unroll
        for (int mt = 0; mt < 2; ++mt)
            #pragma unroll
            for (int nt = 0; nt < 8; ++nt){
                float m01 = fmaxf(c[mt][nt][0], c[mt][nt][1]);
                float m23 = fmaxf(c[mt][nt][2], c[mt][nt][3]);
                m = fmaxf(m, fmaxf(m01, m23));
            }
        #pragma unroll
        for (int off = 16; off > 0; off >>= 1)
            m = fmaxf(m, __shfl_xor_sync(0xffffffffu, m, off));
        if (lane == 0) red[warp] = m;
    }
    __syncthreads();
    if (tid == 0){
        float m = red[0];
        #pragma unroll
        for (int w = 1; w < 8; ++w) m = fmaxf(m, red[w]);
        mpp[0] = m;
    }
    __syncthreads();
    const float mp = mpp[0];

    // ---- spill exp(c - mp) directly into G ----
    #pragma unroll
    for (int mt = 0; mt < 2; ++mt)
        #pragma unroll
        for (int nt = 0; nt < 8; ++nt){
            int row = wm*32 + mt*16 + g;
            int col = wn*64 + nt*8 + tg*2;
            *(float2*)&G[row*GROW + col] =
                make_float2(__expf(c[mt][nt][0]-mp), __expf(c[mt][nt][1]-mp));
            *(float2*)&G[(row+8)*GROW + col] =
                make_float2(__expf(c[mt][nt][2]-mp), __expf(c[mt][nt][3]-mp));
        }
    __syncthreads();

    const int row = tid >> 1, part = tid & 1;

    // ---- row sums (pure adds) ----
    {
        const float* Gr = G + row*GROW + part*64;
        float sum = 0.f;
        #pragma unroll
        for (int q = 0; q < 16; ++q){
            float4 v = *(const float4*)(Gr + q*4);
            sum += (v.x + v.y) + (v.z + v.w);
        }
        sum += __shfl_xor_sync(0xffffffffu, sum, 1);
        if (part == 0){
            rowS[row] = sum;
            int idx = (s*BSZ + aBase + row)*2 + nh;
            g_px2_m[idx] = mp; g_px2_s[idx] = sum;
        }
    }
    __syncthreads();

    // ---- col sums + plane sum ----
    {
        const int col = tid >> 1;
        const float* Gc = G + part*64*GROW + col;
        float sum = 0.f;
        #pragma unroll 8
        for (int rr = 0; rr < 64; ++rr) sum += Gc[rr*GROW];
        sum += __shfl_xor_sync(0xffffffffu, sum, 1);
        if (part == 0){
            int idx = (s*BSZ + rBase + col)*2 + half;
            g_py2_m[idx] = mp; g_py2_s[idx] = sum;
        }
    }
    if (warp < 4){
        float v = rowS[warp*32 + lane];
        #pragma unroll
        for (int off = 16; off > 0; off >>= 1)
            v += __shfl_xor_sync(0xffffffffu, v, off);
        if (lane == 0) red[8 + warp] = v;
    }
    __syncthreads();
    if (tid == 0){
        int idx = s*4 + half*2 + nh;
        g_pz_m[idx] = mp;
        g_pz_s[idx] = (red[8] + red[9]) + (red[10] + red[11]);
    }
}

// ============ finalize: per-line losses + last-block global sum ============
__global__ void finalize(const float* __restrict__ X, const float* __restrict__ Y,
                         const float* __restrict__ Z, float* __restrict__ out){
    __shared__ float wred[8*5];
    __shared__ int lastFlag;
    const int t = blockIdx.x, si = threadIdx.x;
    const int warp = si >> 5, lane = si & 31;

    float Mx = NEG, Sx = 0.f, My = NEG, Sy = 0.f;
    {
        int b = (si*BSZ + t)*2;
        lse_merge(Mx, Sx, g_px2_m[b],   g_px2_s[b]);
        lse_merge(Mx, Sx, g_px2_m[b+1], g_px2_s[b+1]);
        lse_merge(My, Sy, g_py2_m[b],   g_py2_s[b]);
        lse_merge(My, Sy, g_py2_m[b+1], g_py2_s[b+1]);
    }
    float dg = X[t*D + 2*si]   * Y[t*D + 2*si]   * Z[t*D + 2*si]
             + X[t*D + 2*si+1] * Y[t*D + 2*si+1] * Z[t*D + 2*si+1];

    #pragma unroll
    for (int off = 16; off > 0; off >>= 1){
        float m2 = __shfl_xor_sync(0xffffffffu, Mx, off);
        float s2 = __shfl_xor_sync(0xffffffffu, Sx, off);
        lse_merge(Mx, Sx, m2, s2);
        m2 = __shfl_xor_sync(0xffffffffu, My, off);
        s2 = __shfl_xor_sync(0xffffffffu, Sy, off);
        lse_merge(My, Sy, m2, s2);
        dg += __shfl_xor_sync(0xffffffffu, dg, off);
    }
    if (lane == 0){
        wred[warp*5+0] = Mx; wred[warp*5+1] = Sx;
        wred[warp*5+2] = My; wred[warp*5+3] = Sy;
        wred[warp*5+4] = dg;
    }
    __syncthreads();
    if (si == 0){
        float MX = NEG, SX = 0.f, MY = NEG, SY = 0.f, DG = 0.f;
        #pragma unroll
        for (int w = 0; w < 8; ++w){
            lse_merge(MX, SX, wred[w*5+0], wred[w*5+1]);
            lse_merge(MY, SY, wred[w*5+2], wred[w*5+3]);
            DG += wred[w*5+4];
        }
        float MZ = NEG, SZ = 0.f;
        #pragma unroll
        for (int q = 0; q < 4; ++q)
            lse_merge(MZ, SZ, g_pz_m[t*4+q], g_pz_s[t*4+q]);
        g_line[t] = (MX + logf(SX)) + (MY + logf(SY)) + (MZ + logf(SZ)) - 3.f*DG;
        __threadfence();
        lastFlag = (atomicAdd(&g_ctr, 1) == BSZ - 1) ? 1 : 0;
    }
    __syncthreads();
    if (lastFlag){
        if (warp == 0){
            float v = 0.f;
            #pragma unroll
            for (int j = 0; j < 8; ++j) v += g_line[lane + j*32];
            #pragma unroll
            for (int off = 16; off > 0; off >>= 1)
                v += __shfl_xor_sync(0xffffffffu, v, off);
            if (lane == 0){
                out[0] = v / 768.f;
                g_ctr = 0;             // reset for next graph replay
            }
        }
    }
}

extern "C" void kernel_launch(void* const* d_in, const int* in_sizes, int n_in,
                              void* d_out, int out_size){
    const float* X = (const float*)d_in[0];
    const float* Y = (const float*)d_in[1];
    const float* Z = (const float*)d_in[2];
    float* out = (float*)d_out;

    cudaFuncSetAttribute(symile_quad, cudaFuncAttributeMaxDynamicSharedMemorySize, SMEM_BYTES);
    cudaFuncSetAttribute(prep_kernel, cudaFuncAttributeMaxDynamicSharedMemorySize, 65536);

    prep_kernel<<<320, 256, 65536>>>(X, Y, Z);
    symile_quad<<<BSZ*4, 256, SMEM_BYTES>>>();
    finalize<<<BSZ, 256>>>(X, Y, Z, out);
}